// round 8
// baseline (speedup 1.0000x reference)
#include <cuda_runtime.h>

#define BB 256
#define TT 1024
#define DD 128
#define LL 16
#define OO 256

// ---- recurrence geometry: 512 thr = 16 warps = 4 k-chunks x 4 o-quarters
// thread: 64 k-rows x 2 o-cols. 40 k in registers (20 pairs), 24 k via smem (12 pairs).
#define NTHR 512
#define RSM_TSTRIDE 208     // 24 u64 data + 2 u64 pad per thread (13*16B -> conflict-free v2u64)

#define PART_OFF 0          // partial[2 pbuf][4 chunk][2 batch][256 o] f32 = 16 KB
#define S_OFF    16384      // state  [2 pbuf][2 batch][256] f32          = 4 KB
#define RSM_OFF  20480      // Rsm: 512 * 208 = 106496 B
#define SMEM_BYTES (RSM_OFF + NTHR * RSM_TSTRIDE)   // 126976 B

__device__ float g_agg[(size_t)BB * TT * OO];

// ---------------------------------------------------------------------------
// Kernel 1: agg[b,t,o] = sum_l act_l( x[b,t,:]·sub_W[l,:] + sub_b[l] ) * agg_W[l,o]
// 64 rows per CTA (4x fewer CTAs than before -> 4x less agg_W re-read traffic).
// ---------------------------------------------------------------------------
__global__ void __launch_bounds__(256) act_agg_kernel(
    const float* __restrict__ x, const float* __restrict__ subW,
    const float* __restrict__ subb, const float* __restrict__ aggW)
{
    __shared__ float xs[64][DD];          // 32 KB
    __shared__ float ws[LL][DD + 4];      // 8.25 KB
    __shared__ float as_[64][LL + 1];     // 4.25 KB

    const int tid = threadIdx.x;
    const size_t row0 = (size_t)blockIdx.x * 64;

    for (int i = tid; i < LL * DD; i += 256) ws[i / DD][i % DD] = subW[i];
    {
        const float4* xg = (const float4*)(x + row0 * DD);
        float4* xs4 = (float4*)&xs[0][0];
#pragma unroll
        for (int i = 0; i < 8; i++) xs4[tid + 256 * i] = xg[tid + 256 * i];
    }
    __syncthreads();

    {
        const int l = tid & 15, rr = tid >> 4;
        const float bias = subb[l];
        const float4* wr = (const float4*)&ws[l][0];
#pragma unroll
        for (int it = 0; it < 4; it++) {
            const int r = rr + 16 * it;
            const float4* xr = (const float4*)&xs[r][0];
            float acc = 0.f;
#pragma unroll
            for (int i = 0; i < DD / 4; i++) {
                float4 a = xr[i], b = wr[i];
                acc += a.x * b.x; acc += a.y * b.y; acc += a.z * b.z; acc += a.w * b.w;
            }
            acc += bias;
            float v;
            const int m = l & 3;
            if (m == 0)      v = tanhf(acc);
            else if (m == 1) v = fmaxf(acc, 0.f);
            else if (m == 2) v = 1.f / (1.f + expf(-acc));
            else             v = acc;
            as_[r][l] = v;
        }
    }
    __syncthreads();

    {
        const int o = tid;
        float wcol[LL];
#pragma unroll
        for (int l = 0; l < LL; l++) wcol[l] = aggW[l * OO + o];
        float* outp = g_agg + row0 * OO + o;
#pragma unroll
        for (int r = 0; r < 64; r++) {
            float acc = 0.f;
#pragma unroll
            for (int l = 0; l < LL; l++) acc += as_[r][l] * wcol[l];
            outp[(size_t)r * OO] = acc;
        }
    }
}

// ---------------------------------------------------------------------------
// Kernel 2: recurrence s_t = agg_t + s_{t-1} @ R
//   warp w (of 16): k-chunk c = w&3 (rows 64c..64c+63), o-quarter q = w>>2
//   lane: o-cols { q*64 + lane, q*64 + lane + 32 }
//   R packed as (k,k+1) f32x2 pairs; accs hold even/odd-k halves in f32x2 lanes.
// ---------------------------------------------------------------------------
#define FMA2(acc, a, b) asm("fma.rn.f32x2 %0, %1, %2, %0;" : "+l"(acc) : "l"(a), "l"(b))

__device__ __forceinline__ void lds_v2u64(unsigned long long& a, unsigned long long& b,
                                          unsigned int addr) {
    asm volatile("ld.shared.v2.u64 {%0, %1}, [%2];" : "=l"(a), "=l"(b) : "r"(addr));
}
__device__ __forceinline__ float lds_f32(unsigned int addr) {
    float v; asm volatile("ld.shared.f32 %0, [%1];" : "=f"(v) : "r"(addr)); return v;
}
__device__ __forceinline__ void sts_f32(unsigned int addr, float v) {
    asm volatile("st.shared.f32 [%0], %1;" :: "r"(addr), "f"(v));
}
__device__ __forceinline__ void sts_u64(unsigned int addr, unsigned long long v) {
    asm volatile("st.shared.u64 [%0], %1;" :: "r"(addr), "l"(v));
}

__global__ void __launch_bounds__(NTHR, 1) recur_kernel(const float* __restrict__ R,
                                                        float* __restrict__ out)
{
    extern __shared__ unsigned char dyn[];
    unsigned int sm;
    asm("{ .reg .u64 t0; cvta.to.shared.u64 t0, %1; cvt.u32.u64 %0, t0; }"
        : "=r"(sm) : "l"(dyn));

    const int tid  = threadIdx.x;
    const int lane = tid & 31;
    const int w    = tid >> 5;
    const int c    = w & 3;        // k-chunk: rows 64c .. 64c+63
    const int q    = w >> 2;       // o-quarter: cols 64q .. 64q+63
    const int b0   = blockIdx.x * 2;

    // ---- 20 k-pairs (40 rows) x 2 o-cols into registers
    unsigned long long Rp[40];
#pragma unroll
    for (int i = 0; i < 20; i++)
#pragma unroll
        for (int j = 0; j < 2; j++) {
            const int k = c * 64 + 2 * i;
            const int o = q * 64 + lane + 32 * j;
            float lo = R[(size_t)k * OO + o];
            float hi = R[(size_t)(k + 1) * OO + o];
            asm("mov.b64 %0, {%1, %2};" : "=l"(Rp[i * 2 + j]) : "f"(lo), "f"(hi));
        }

    // ---- 12 k-pairs (24 rows) x 2 o-cols into per-thread smem rows
    const unsigned int rsm = sm + RSM_OFF + tid * RSM_TSTRIDE;
#pragma unroll
    for (int m = 0; m < 12; m++)
#pragma unroll
        for (int j = 0; j < 2; j++) {
            const int k = c * 64 + 40 + 2 * m;
            const int o = q * 64 + lane + 32 * j;
            float lo = R[(size_t)k * OO + o];
            float hi = R[(size_t)(k + 1) * OO + o];
            unsigned long long p;
            asm("mov.b64 %0, {%1, %2};" : "=l"(p) : "f"(lo), "f"(hi));
            sts_u64(rsm + (unsigned)(m * 16 + j * 8), p);
        }

    // zero initial state in buffer 0 ([2 batch][256] = 512 floats, one per thread)
    sts_f32(sm + S_OFF + tid * 4, 0.f);

    // phase-2 identity: thread -> (output column ot, batch bt)
    const int ot = tid & 255;
    const int bt = tid >> 8;
    const float* aggp = g_agg + ((size_t)(b0 + bt) * TT) * OO + ot;
    float*       outp = out   + ((size_t)(b0 + bt) * TT) * OO + ot;
    float a_cur = __ldg(aggp);

    const unsigned int pw_base = sm + PART_OFF + c * 2048 + (q * 64 + lane) * 4;
    const unsigned int pr_base = sm + PART_OFF + bt * 1024 + ot * 4;
    const unsigned int sw_base = sm + S_OFF + bt * 1024 + ot * 4;
    const unsigned int sc_base = sm + S_OFF + c * 256;

    __syncthreads();

    for (int t = 0; t < TT; t++) {
        const int p = t & 1;
        float a_nxt = 0.f;
        if (t + 1 < TT) a_nxt = __ldg(aggp + (size_t)(t + 1) * OO);

        const unsigned int sA = sc_base + p * 2048;   // batch A state chunk
        const unsigned int sB = sA + 1024;            // batch B

        unsigned long long aA0 = 0, aA1 = 0, aB0 = 0, aB1 = 0;

        // -------- phase 1a: 20 register k-pairs (2 pairs per iter) --------
#pragma unroll
        for (int ii = 0; ii < 10; ii++) {
            unsigned long long ax, ay, bx, by;
            lds_v2u64(ax, ay, sA + ii * 16);          // pairs 2ii, 2ii+1 (batch A)
            lds_v2u64(bx, by, sB + ii * 16);          // batch B
            FMA2(aA0, ax, Rp[(2*ii)*2+0]);   FMA2(aA1, ax, Rp[(2*ii)*2+1]);
            FMA2(aB0, bx, Rp[(2*ii)*2+0]);   FMA2(aB1, bx, Rp[(2*ii)*2+1]);
            FMA2(aA0, ay, Rp[(2*ii+1)*2+0]); FMA2(aA1, ay, Rp[(2*ii+1)*2+1]);
            FMA2(aB0, by, Rp[(2*ii+1)*2+0]); FMA2(aB1, by, Rp[(2*ii+1)*2+1]);
        }
        // -------- phase 1b: 12 smem k-pairs (2 pairs per iter) --------
#pragma unroll
        for (int ii = 10; ii < 16; ii++) {
            unsigned long long ax, ay, bx, by, r0, r1;
            lds_v2u64(ax, ay, sA + ii * 16);
            lds_v2u64(bx, by, sB + ii * 16);
            lds_v2u64(r0, r1, rsm + (2*ii - 20) * 16);
            FMA2(aA0, ax, r0); FMA2(aA1, ax, r1);
            FMA2(aB0, bx, r0); FMA2(aB1, bx, r1);
            lds_v2u64(r0, r1, rsm + (2*ii - 19) * 16);
            FMA2(aA0, ay, r0); FMA2(aA1, ay, r1);
            FMA2(aB0, by, r0); FMA2(aB1, by, r1);
        }

        // fold even/odd-k halves, store 4 partials (coalesced STS.32)
        {
            const unsigned int pw = pw_base + p * 8192;
            float x, y;
            asm("mov.b64 {%0,%1}, %2;" : "=f"(x), "=f"(y) : "l"(aA0)); sts_f32(pw,               x + y);
            asm("mov.b64 {%0,%1}, %2;" : "=f"(x), "=f"(y) : "l"(aA1)); sts_f32(pw + 128,         x + y);
            asm("mov.b64 {%0,%1}, %2;" : "=f"(x), "=f"(y) : "l"(aB0)); sts_f32(pw + 1024,        x + y);
            asm("mov.b64 {%0,%1}, %2;" : "=f"(x), "=f"(y) : "l"(aB1)); sts_f32(pw + 1024 + 128,  x + y);
        }
        __syncthreads();

        // -------- phase 2: one (o,batch) per thread: reduce 4 chunks, publish
        {
            const unsigned int pr = pr_base + p * 8192;
            float r = a_cur + lds_f32(pr)
                            + lds_f32(pr + 2048)
                            + lds_f32(pr + 4096)
                            + lds_f32(pr + 6144);
            sts_f32(sw_base + (p ^ 1) * 2048, r);
            outp[(size_t)t * OO] = r;
        }
        a_cur = a_nxt;
        __syncthreads();
    }
}

// ---------------------------------------------------------------------------
extern "C" void kernel_launch(void* const* d_in, const int* in_sizes, int n_in,
                              void* d_out, int out_size)
{
    const float* x    = (const float*)d_in[0];
    const float* subW = (const float*)d_in[1];
    const float* subb = (const float*)d_in[2];
    const float* aggW = (const float*)d_in[3];
    const float* R    = (const float*)d_in[4];
    float* out = (float*)d_out;

    cudaFuncSetAttribute(recur_kernel, cudaFuncAttributeMaxDynamicSharedMemorySize,
                         SMEM_BYTES);

    act_agg_kernel<<<(BB * TT) / 64, 256>>>(x, subW, subb, aggW);
    recur_kernel<<<BB / 2, NTHR, SMEM_BYTES>>>(R, out);
}